// round 1
// baseline (speedup 1.0000x reference)
#include <cuda_runtime.h>
#include <math_constants.h>

#define NN   50000
#define EE   800000
#define INC  64
#define HID  256
#define NH   4
#define OUTC 64
#define NCLS 10
#define NG   64

// ---------------- scratch (static device globals: no allocs) ----------------
__device__ float g_h [(size_t)NN * HID];   // per-layer linear output
__device__ float g_x1[(size_t)NN * HID];
__device__ float g_x2[(size_t)NN * HID];
__device__ float g_x3[(size_t)NN * HID];   // holds x3 + x1 (residual fused)
__device__ float g_ssrc[NN * NH];
__device__ float g_sdst[NN * NH];
__device__ int   g_cnt[NN];
__device__ int   g_off[NN + 1];
__device__ int   g_cur[NN];
__device__ int   g_esrc[EE];
__device__ float g_pool[NG * HID];
__device__ float g_gcnt[NG];

// ---------------- init / CSR build ----------------
__global__ void k_init() {
    int i = blockIdx.x * blockDim.x + threadIdx.x;
    if (i < NN) g_cnt[i] = 0;
    if (i < NG * HID) g_pool[i] = 0.f;
    if (i < NG) g_gcnt[i] = 0.f;
}

__global__ void k_count(const int* __restrict__ ei) {
    int e = blockIdx.x * blockDim.x + threadIdx.x;
    if (e >= EE) return;
    atomicAdd(&g_cnt[ei[EE + e]], 1);
}

__global__ void k_scan() {
    __shared__ int sp[1024];
    int tid = threadIdx.x;
    const int CH = (NN + 1023) / 1024;
    int base = tid * CH;
    int lim = NN - base; if (lim < 0) lim = 0; if (lim > CH) lim = CH;
    int sum = 0;
    for (int i = 0; i < lim; i++) sum += g_cnt[base + i];
    sp[tid] = sum;
    __syncthreads();
    for (int off = 1; off < 1024; off <<= 1) {
        int v = (tid >= off) ? sp[tid - off] : 0;
        __syncthreads();
        sp[tid] += v;
        __syncthreads();
    }
    int run = sp[tid] - sum;   // exclusive prefix
    for (int i = 0; i < lim; i++) {
        g_off[base + i] = run;
        g_cur[base + i] = run;
        run += g_cnt[base + i];
    }
    if (tid == 1023) g_off[NN] = run;
}

__global__ void k_scatter(const int* __restrict__ ei) {
    int e = blockIdx.x * blockDim.x + threadIdx.x;
    if (e >= EE) return;
    int d = ei[EE + e];
    int pos = atomicAdd(&g_cur[d], 1);
    g_esrc[pos] = ei[e];
}

// ---------------- SGEMM: C[NN,256] = A[NN,K] @ B[K,256] ----------------
// 64x64 tile, BK=16, 256 threads, 4x4 register blocking.
__global__ void k_gemm(const float* __restrict__ Aext, const float* __restrict__ B,
                       int K, int asel) {
    const float* A = (asel == 0) ? Aext : (asel == 1 ? g_x1 : g_x2);
    __shared__ float Ast[16][68];   // transposed A tile, padded
    __shared__ float Bs [16][64];
    int tid = threadIdx.x;
    int tx = tid & 15, ty = tid >> 4;
    int bm = blockIdx.x, bn = blockIdx.y;
    int ar = tid >> 2;            // 0..63
    int ac = (tid & 3) << 2;      // 0,4,8,12
    int br = tid >> 4;            // 0..15
    int bc = (tid & 15) << 2;     // 0..60
    float c[4][4];
#pragma unroll
    for (int i = 0; i < 4; i++)
#pragma unroll
        for (int j = 0; j < 4; j++) c[i][j] = 0.f;

    int arow = bm * 64 + ar;
    const float* Arow = A + (size_t)arow * K;
    for (int kk = 0; kk < K; kk += 16) {
        float4 av = make_float4(0.f, 0.f, 0.f, 0.f);
        if (arow < NN) av = *(const float4*)(Arow + kk + ac);
        Ast[ac + 0][ar] = av.x; Ast[ac + 1][ar] = av.y;
        Ast[ac + 2][ar] = av.z; Ast[ac + 3][ar] = av.w;
        *(float4*)&Bs[br][bc] = *(const float4*)(B + (size_t)(kk + br) * HID + bn * 64 + bc);
        __syncthreads();
#pragma unroll
        for (int k = 0; k < 16; k++) {
            float4 a4 = *(const float4*)&Ast[k][ty << 2];
            float4 b4 = *(const float4*)&Bs[k][tx << 2];
            float a[4] = {a4.x, a4.y, a4.z, a4.w};
            float b[4] = {b4.x, b4.y, b4.z, b4.w};
#pragma unroll
            for (int i = 0; i < 4; i++)
#pragma unroll
                for (int j = 0; j < 4; j++)
                    c[i][j] = fmaf(a[i], b[j], c[i][j]);
        }
        __syncthreads();
    }
#pragma unroll
    for (int i = 0; i < 4; i++) {
        int row = bm * 64 + (ty << 2) + i;
        if (row < NN) {
            float4 v = make_float4(c[i][0], c[i][1], c[i][2], c[i][3]);
            *(float4*)(g_h + (size_t)row * HID + bn * 64 + (tx << 2)) = v;
        }
    }
}

// ---------------- per-node attention logits: s = einsum(h, a) ----------------
__global__ void k_score(const float* __restrict__ asrc, const float* __restrict__ adst) {
    int t = blockIdx.x * blockDim.x + threadIdx.x;
    int w = t >> 5, lane = t & 31;
    if (w >= NN) return;
    int head = lane >> 3, sub = lane & 7;
    const float4* hp = (const float4*)(g_h + (size_t)w * HID + lane * 8);
    float4 v0 = hp[0], v1 = hp[1];
    const float4* ap = (const float4*)(asrc + head * OUTC + sub * 8);
    const float4* dp = (const float4*)(adst + head * OUTC + sub * 8);
    float4 a0 = ap[0], a1 = ap[1];
    float4 d0 = dp[0], d1 = dp[1];
    float ps = v0.x * a0.x + v0.y * a0.y + v0.z * a0.z + v0.w * a0.w
             + v1.x * a1.x + v1.y * a1.y + v1.z * a1.z + v1.w * a1.w;
    float pd = v0.x * d0.x + v0.y * d0.y + v0.z * d0.z + v0.w * d0.w
             + v1.x * d1.x + v1.y * d1.y + v1.z * d1.z + v1.w * d1.w;
#pragma unroll
    for (int o = 4; o; o >>= 1) {
        ps += __shfl_down_sync(0xffffffffu, ps, o, 8);
        pd += __shfl_down_sync(0xffffffffu, pd, o, 8);
    }
    if (sub == 0) { g_ssrc[w * NH + head] = ps; g_sdst[w * NH + head] = pd; }
}

// ---------------- warp-per-dst online-softmax aggregation (no atomics) ------
// outsel: 1->g_x1, 2->g_x2, 3->g_x3 (with residual += g_x1)
__global__ void k_agg(const float* __restrict__ bias, int outsel) {
    int t = blockIdx.x * blockDim.x + threadIdx.x;
    int w = t >> 5, lane = t & 31;
    if (w >= NN) return;
    float* outbuf = (outsel == 1) ? g_x1 : (outsel == 2 ? g_x2 : g_x3);
    int head = lane >> 3;
    float sd = g_sdst[w * NH + head];
    int s = g_off[w], e = g_off[w + 1];
    float m = -CUDART_INF_F, d = 0.f;
    float acc[8];
#pragma unroll
    for (int j = 0; j < 8; j++) acc[j] = 0.f;

    for (int i = s; i <= e; i++) {               // i==e -> self loop
        int src = (i < e) ? g_esrc[i] : w;
        float ev = __ldg(&g_ssrc[src * NH + head]) + sd;
        ev = fmaxf(ev, 0.2f * ev);               // leaky_relu(0.2)
        float mn = fmaxf(m, ev);
        float scale = __expf(m - mn);            // exp(-inf)=0 on first iter
        float p = __expf(ev - mn);
        d = d * scale + p;
        const float4* hp = (const float4*)(g_h + (size_t)src * HID + lane * 8);
        float4 h0 = hp[0], h1 = hp[1];
        acc[0] = fmaf(acc[0], scale, p * h0.x);
        acc[1] = fmaf(acc[1], scale, p * h0.y);
        acc[2] = fmaf(acc[2], scale, p * h0.z);
        acc[3] = fmaf(acc[3], scale, p * h0.w);
        acc[4] = fmaf(acc[4], scale, p * h1.x);
        acc[5] = fmaf(acc[5], scale, p * h1.y);
        acc[6] = fmaf(acc[6], scale, p * h1.z);
        acc[7] = fmaf(acc[7], scale, p * h1.w);
        m = mn;
    }
    float inv = 1.f / d;
    int cb = lane * 8;
    float4 bb0 = *(const float4*)(bias + cb);
    float4 bb1 = *(const float4*)(bias + cb + 4);
    float o[8];
    o[0] = fmaxf(acc[0] * inv + bb0.x, 0.f);
    o[1] = fmaxf(acc[1] * inv + bb0.y, 0.f);
    o[2] = fmaxf(acc[2] * inv + bb0.z, 0.f);
    o[3] = fmaxf(acc[3] * inv + bb0.w, 0.f);
    o[4] = fmaxf(acc[4] * inv + bb1.x, 0.f);
    o[5] = fmaxf(acc[5] * inv + bb1.y, 0.f);
    o[6] = fmaxf(acc[6] * inv + bb1.z, 0.f);
    o[7] = fmaxf(acc[7] * inv + bb1.w, 0.f);
    if (outsel == 3) {
        const float4* rp = (const float4*)(g_x1 + (size_t)w * HID + cb);
        float4 r0 = rp[0], r1 = rp[1];
        o[0] += r0.x; o[1] += r0.y; o[2] += r0.z; o[3] += r0.w;
        o[4] += r1.x; o[5] += r1.y; o[6] += r1.z; o[7] += r1.w;
    }
    *(float4*)(outbuf + (size_t)w * HID + cb)     = make_float4(o[0], o[1], o[2], o[3]);
    *(float4*)(outbuf + (size_t)w * HID + cb + 4) = make_float4(o[4], o[5], o[6], o[7]);
}

// ---------------- global mean pool (run-length chunked atomics) -------------
__global__ void k_pool(const int* __restrict__ batch) {
    const int CHUNK = 128;
    int n0 = blockIdx.x * CHUNK;
    int c = threadIdx.x;                  // channel 0..255
    float acc = 0.f, cnt = 0.f;
    int curg = -1;
    int nend = n0 + CHUNK; if (nend > NN) nend = NN;
    for (int n = n0; n < nend; n++) {
        int g = batch[n];
        if (g != curg) {
            if (curg >= 0) {
                atomicAdd(&g_pool[curg * HID + c], acc);
                if (c == 0) atomicAdd(&g_gcnt[curg], cnt);
            }
            curg = g; acc = 0.f; cnt = 0.f;
        }
        acc += g_x3[(size_t)n * HID + c];
        cnt += 1.f;
    }
    if (curg >= 0) {
        atomicAdd(&g_pool[curg * HID + c], acc);
        if (c == 0) atomicAdd(&g_gcnt[curg], cnt);
    }
}

// ---------------- final FC ----------------
__global__ void k_fc(const float* __restrict__ fcW, const float* __restrict__ fcb,
                     float* __restrict__ out) {
    int idx = blockIdx.x * blockDim.x + threadIdx.x;
    if (idx >= NG * NCLS) return;
    int g = idx / NCLS, c = idx % NCLS;
    float cnt = fmaxf(g_gcnt[g], 1.f);
    float s = 0.f;
    for (int k = 0; k < HID; k++) s += g_pool[g * HID + k] * fcW[k * NCLS + c];
    out[idx] = s / cnt + fcb[c];
}

// ---------------- launch ----------------
extern "C" void kernel_launch(void* const* d_in, const int* in_sizes, int n_in,
                              void* d_out, int out_size) {
    (void)in_sizes; (void)n_in; (void)out_size;
    const float* x   = (const float*)d_in[0];
    const int*   ei  = (const int*)d_in[1];
    const int*   bat = (const int*)d_in[2];
    const float* W1  = (const float*)d_in[3];
    const float* as1 = (const float*)d_in[4];
    const float* ad1 = (const float*)d_in[5];
    const float* b1  = (const float*)d_in[6];
    const float* W2  = (const float*)d_in[7];
    const float* as2 = (const float*)d_in[8];
    const float* ad2 = (const float*)d_in[9];
    const float* b2  = (const float*)d_in[10];
    const float* W3  = (const float*)d_in[11];
    const float* as3 = (const float*)d_in[12];
    const float* ad3 = (const float*)d_in[13];
    const float* b3  = (const float*)d_in[14];
    const float* fcW = (const float*)d_in[15];
    const float* fcb = (const float*)d_in[16];
    float* out = (float*)d_out;

    // CSR build + zeroing
    k_init   <<<(NN + 255) / 256, 256>>>();
    k_count  <<<(EE + 255) / 256, 256>>>(ei);
    k_scan   <<<1, 1024>>>();
    k_scatter<<<(EE + 255) / 256, 256>>>(ei);

    dim3 ggrid((NN + 63) / 64, HID / 64);
    int wblocks = (NN * 32 + 255) / 256;

    // layer 1: A = x (K=64)
    k_gemm <<<ggrid, 256>>>(x, W1, INC, 0);
    k_score<<<wblocks, 256>>>(as1, ad1);
    k_agg  <<<wblocks, 256>>>(b1, 1);

    // layer 2: A = g_x1 (K=256)
    k_gemm <<<ggrid, 256>>>(x, W2, HID, 1);
    k_score<<<wblocks, 256>>>(as2, ad2);
    k_agg  <<<wblocks, 256>>>(b2, 2);

    // layer 3: A = g_x2 (K=256), residual += g_x1
    k_gemm <<<ggrid, 256>>>(x, W3, HID, 2);
    k_score<<<wblocks, 256>>>(as3, ad3);
    k_agg  <<<wblocks, 256>>>(b3, 3);

    // pool + fc
    k_pool<<<(NN + 127) / 128, 256>>>(bat);
    k_fc  <<<(NG * NCLS + 255) / 256, 256>>>(fcW, fcb, out);
}

// round 2
// speedup vs baseline: 1.1688x; 1.1688x over previous
#include <cuda_runtime.h>
#include <math_constants.h>

#define NN   50000
#define EE   800000
#define INC  64
#define HID  256
#define NH   4
#define OUTC 64
#define NCLS 10
#define NG   64

#define SCAN_B 512
#define SCAN_NB ((NN + SCAN_B - 1) / SCAN_B)   // 98

// ---------------- scratch (static device globals: no allocs) ----------------
__device__ float g_h [(size_t)NN * HID];   // per-layer linear output
__device__ float g_x1[(size_t)NN * HID];
__device__ float g_x2[(size_t)NN * HID];
__device__ float g_x3[(size_t)NN * HID];   // holds x3 + x1 (residual fused)
__device__ float g_ssrc[NN * NH];
__device__ float g_sdst[NN * NH];
__device__ int   g_cnt[NN];
__device__ int   g_off[NN + 1];
__device__ int   g_cur[NN];
__device__ int   g_esrc[EE];
__device__ int   g_bsum[SCAN_NB];
__device__ int   g_bbase[SCAN_NB];
__device__ float g_pool[NG * HID];
__device__ float g_gcnt[NG];

// ---------------- init / CSR build ----------------
__global__ void k_init() {
    int i = blockIdx.x * blockDim.x + threadIdx.x;
    if (i < NN) g_cnt[i] = 0;
    if (i < NG * HID) g_pool[i] = 0.f;
    if (i < NG) g_gcnt[i] = 0.f;
}

__global__ void k_count(const int* __restrict__ ei) {
    int e = blockIdx.x * blockDim.x + threadIdx.x;
    if (e >= EE) return;
    atomicAdd(&g_cnt[ei[EE + e]], 1);
}

__global__ void k_bsum() {
    __shared__ int sh[SCAN_B];
    int b = blockIdx.x, t = threadIdx.x;
    int i = b * SCAN_B + t;
    sh[t] = (i < NN) ? g_cnt[i] : 0;
    __syncthreads();
    for (int o = SCAN_B / 2; o > 0; o >>= 1) {
        if (t < o) sh[t] += sh[t + o];
        __syncthreads();
    }
    if (t == 0) g_bsum[b] = sh[0];
}

__global__ void k_bscan() {
    __shared__ int sh[128];
    int t = threadIdx.x;
    int v = (t < SCAN_NB) ? g_bsum[t] : 0;
    sh[t] = v;
    __syncthreads();
    for (int o = 1; o < 128; o <<= 1) {
        int u = (t >= o) ? sh[t - o] : 0;
        __syncthreads();
        sh[t] += u;
        __syncthreads();
    }
    if (t < SCAN_NB) g_bbase[t] = sh[t] - v;   // exclusive block base
    if (t == 0) g_off[NN] = EE;
}

__global__ void k_csr() {
    __shared__ int sh[SCAN_B];
    int b = blockIdx.x, t = threadIdx.x;
    int i = b * SCAN_B + t;
    int v = (i < NN) ? g_cnt[i] : 0;
    sh[t] = v;
    __syncthreads();
    for (int o = 1; o < SCAN_B; o <<= 1) {   // inclusive Hillis-Steele
        int u = (t >= o) ? sh[t - o] : 0;
        __syncthreads();
        sh[t] += u;
        __syncthreads();
    }
    if (i < NN) {
        int excl = g_bbase[b] + sh[t] - v;
        g_off[i] = excl;
        g_cur[i] = excl;
    }
}

__global__ void k_scatter(const int* __restrict__ ei) {
    int e = blockIdx.x * blockDim.x + threadIdx.x;
    if (e >= EE) return;
    int d = ei[EE + e];
    int pos = atomicAdd(&g_cur[d], 1);
    g_esrc[pos] = ei[e];
}

// ---------------- SGEMM: g_h[NN,256] = A[NN,K] @ B[K,256] ----------------
// 128x128 tile, BK=8, 256 threads, 8x8 microtile, reg-prefetch double buffer.
__global__ __launch_bounds__(256, 2)
void k_gemm(const float* __restrict__ Aext, const float* __restrict__ B,
            int K, int asel) {
    const float* A = (asel == 0) ? Aext : (asel == 1 ? g_x1 : g_x2);
    __shared__ float As[2][8][128];
    __shared__ float Bs[2][8][128];
    int tid = threadIdx.x;
    int tx = tid & 15, ty = tid >> 4;
    int bm = blockIdx.x * 128;
    int bn = blockIdx.y * 128;

    int arow = tid >> 1;           // 0..127
    int acol = (tid & 1) << 2;     // 0 or 4
    int brow = tid >> 5;           // 0..7
    int bcol = (tid & 31) << 2;    // 0..124

    bool aval = (bm + arow) < NN;
    const float* Aptr = A + (size_t)(bm + arow) * K + acol;
    const float* Bptr = B + (size_t)brow * HID + bn + bcol;

    float4 ra = aval ? *(const float4*)Aptr : make_float4(0.f, 0.f, 0.f, 0.f);
    float4 rb = *(const float4*)Bptr;
    As[0][acol + 0][arow] = ra.x;
    As[0][acol + 1][arow] = ra.y;
    As[0][acol + 2][arow] = ra.z;
    As[0][acol + 3][arow] = ra.w;
    *(float4*)&Bs[0][brow][bcol] = rb;
    __syncthreads();

    float c[8][8];
#pragma unroll
    for (int i = 0; i < 8; i++)
#pragma unroll
        for (int j = 0; j < 8; j++) c[i][j] = 0.f;

    int nk = K >> 3;
    int buf = 0;
    for (int t = 0; t < nk; t++) {
        float4 na = make_float4(0.f, 0.f, 0.f, 0.f), nb;
        bool more = (t + 1 < nk);
        if (more) {
            int kk = (t + 1) << 3;
            if (aval) na = *(const float4*)(Aptr + kk);
            nb = *(const float4*)(Bptr + (size_t)kk * HID);
        }
#pragma unroll
        for (int k = 0; k < 8; k++) {
            float4 a0 = *(const float4*)&As[buf][k][ty << 2];
            float4 a1 = *(const float4*)&As[buf][k][64 + (ty << 2)];
            float4 b0 = *(const float4*)&Bs[buf][k][tx << 2];
            float4 b1 = *(const float4*)&Bs[buf][k][64 + (tx << 2)];
            float av[8] = {a0.x, a0.y, a0.z, a0.w, a1.x, a1.y, a1.z, a1.w};
            float bv[8] = {b0.x, b0.y, b0.z, b0.w, b1.x, b1.y, b1.z, b1.w};
#pragma unroll
            for (int i = 0; i < 8; i++)
#pragma unroll
                for (int j = 0; j < 8; j++)
                    c[i][j] = fmaf(av[i], bv[j], c[i][j]);
        }
        if (more) {
            buf ^= 1;
            As[buf][acol + 0][arow] = na.x;
            As[buf][acol + 1][arow] = na.y;
            As[buf][acol + 2][arow] = na.z;
            As[buf][acol + 3][arow] = na.w;
            *(float4*)&Bs[buf][brow][bcol] = nb;
            __syncthreads();
        }
    }

#pragma unroll
    for (int i = 0; i < 8; i++) {
        int row = bm + ((i < 4) ? (ty << 2) + i : 64 + (ty << 2) + (i - 4));
        if (row < NN) {
            float* outp = g_h + (size_t)row * HID + bn;
            *(float4*)(outp + (tx << 2))      = make_float4(c[i][0], c[i][1], c[i][2], c[i][3]);
            *(float4*)(outp + 64 + (tx << 2)) = make_float4(c[i][4], c[i][5], c[i][6], c[i][7]);
        }
    }
}

// ---------------- per-node attention logits: s = einsum(h, a) ----------------
__global__ void k_score(const float* __restrict__ asrc, const float* __restrict__ adst) {
    int t = blockIdx.x * blockDim.x + threadIdx.x;
    int w = t >> 5, lane = t & 31;
    if (w >= NN) return;
    int head = lane >> 3, sub = lane & 7;
    const float4* hp = (const float4*)(g_h + (size_t)w * HID + lane * 8);
    float4 v0 = hp[0], v1 = hp[1];
    const float4* ap = (const float4*)(asrc + head * OUTC + sub * 8);
    const float4* dp = (const float4*)(adst + head * OUTC + sub * 8);
    float4 a0 = ap[0], a1 = ap[1];
    float4 d0 = dp[0], d1 = dp[1];
    float ps = v0.x * a0.x + v0.y * a0.y + v0.z * a0.z + v0.w * a0.w
             + v1.x * a1.x + v1.y * a1.y + v1.z * a1.z + v1.w * a1.w;
    float pd = v0.x * d0.x + v0.y * d0.y + v0.z * d0.z + v0.w * d0.w
             + v1.x * d1.x + v1.y * d1.y + v1.z * d1.z + v1.w * d1.w;
#pragma unroll
    for (int o = 4; o; o >>= 1) {
        ps += __shfl_down_sync(0xffffffffu, ps, o, 8);
        pd += __shfl_down_sync(0xffffffffu, pd, o, 8);
    }
    if (sub == 0) { g_ssrc[w * NH + head] = ps; g_sdst[w * NH + head] = pd; }
}

// ---------------- warp-per-dst online-softmax aggregation (no atomics) ------
__global__ void k_agg(const float* __restrict__ bias, int outsel) {
    int t = blockIdx.x * blockDim.x + threadIdx.x;
    int w = t >> 5, lane = t & 31;
    if (w >= NN) return;
    float* outbuf = (outsel == 1) ? g_x1 : (outsel == 2 ? g_x2 : g_x3);
    int head = lane >> 3;
    float sd = g_sdst[w * NH + head];
    int s = g_off[w], e = g_off[w + 1];
    float m = -CUDART_INF_F, d = 0.f;
    float acc[8];
#pragma unroll
    for (int j = 0; j < 8; j++) acc[j] = 0.f;

    for (int i = s; i <= e; i++) {               // i==e -> self loop
        int src = (i < e) ? g_esrc[i] : w;
        float ev = __ldg(&g_ssrc[src * NH + head]) + sd;
        ev = fmaxf(ev, 0.2f * ev);               // leaky_relu(0.2)
        float mn = fmaxf(m, ev);
        float scale = __expf(m - mn);            // exp(-inf)=0 on first iter
        float p = __expf(ev - mn);
        d = d * scale + p;
        const float4* hp = (const float4*)(g_h + (size_t)src * HID + lane * 8);
        float4 h0 = hp[0], h1 = hp[1];
        acc[0] = fmaf(acc[0], scale, p * h0.x);
        acc[1] = fmaf(acc[1], scale, p * h0.y);
        acc[2] = fmaf(acc[2], scale, p * h0.z);
        acc[3] = fmaf(acc[3], scale, p * h0.w);
        acc[4] = fmaf(acc[4], scale, p * h1.x);
        acc[5] = fmaf(acc[5], scale, p * h1.y);
        acc[6] = fmaf(acc[6], scale, p * h1.z);
        acc[7] = fmaf(acc[7], scale, p * h1.w);
        m = mn;
    }
    float inv = 1.f / d;
    int cb = lane * 8;
    float4 bb0 = *(const float4*)(bias + cb);
    float4 bb1 = *(const float4*)(bias + cb + 4);
    float o[8];
    o[0] = fmaxf(acc[0] * inv + bb0.x, 0.f);
    o[1] = fmaxf(acc[1] * inv + bb0.y, 0.f);
    o[2] = fmaxf(acc[2] * inv + bb0.z, 0.f);
    o[3] = fmaxf(acc[3] * inv + bb0.w, 0.f);
    o[4] = fmaxf(acc[4] * inv + bb1.x, 0.f);
    o[5] = fmaxf(acc[5] * inv + bb1.y, 0.f);
    o[6] = fmaxf(acc[6] * inv + bb1.z, 0.f);
    o[7] = fmaxf(acc[7] * inv + bb1.w, 0.f);
    if (outsel == 3) {
        const float4* rp = (const float4*)(g_x1 + (size_t)w * HID + cb);
        float4 r0 = rp[0], r1 = rp[1];
        o[0] += r0.x; o[1] += r0.y; o[2] += r0.z; o[3] += r0.w;
        o[4] += r1.x; o[5] += r1.y; o[6] += r1.z; o[7] += r1.w;
    }
    *(float4*)(outbuf + (size_t)w * HID + cb)     = make_float4(o[0], o[1], o[2], o[3]);
    *(float4*)(outbuf + (size_t)w * HID + cb + 4) = make_float4(o[4], o[5], o[6], o[7]);
}

// ---------------- global mean pool (run-length chunked atomics) -------------
__global__ void k_pool(const int* __restrict__ batch) {
    const int CHUNK = 128;
    int n0 = blockIdx.x * CHUNK;
    int c = threadIdx.x;                  // channel 0..255
    float acc = 0.f, cnt = 0.f;
    int curg = -1;
    int nend = n0 + CHUNK; if (nend > NN) nend = NN;
    for (int n = n0; n < nend; n++) {
        int g = batch[n];
        if (g != curg) {
            if (curg >= 0) {
                atomicAdd(&g_pool[curg * HID + c], acc);
                if (c == 0) atomicAdd(&g_gcnt[curg], cnt);
            }
            curg = g; acc = 0.f; cnt = 0.f;
        }
        acc += g_x3[(size_t)n * HID + c];
        cnt += 1.f;
    }
    if (curg >= 0) {
        atomicAdd(&g_pool[curg * HID + c], acc);
        if (c == 0) atomicAdd(&g_gcnt[curg], cnt);
    }
}

// ---------------- final FC ----------------
__global__ void k_fc(const float* __restrict__ fcW, const float* __restrict__ fcb,
                     float* __restrict__ out) {
    int idx = blockIdx.x * blockDim.x + threadIdx.x;
    if (idx >= NG * NCLS) return;
    int g = idx / NCLS, c = idx % NCLS;
    float cnt = fmaxf(g_gcnt[g], 1.f);
    float s = 0.f;
    for (int k = 0; k < HID; k++) s += g_pool[g * HID + k] * fcW[k * NCLS + c];
    out[idx] = s / cnt + fcb[c];
}

// ---------------- launch ----------------
extern "C" void kernel_launch(void* const* d_in, const int* in_sizes, int n_in,
                              void* d_out, int out_size) {
    (void)in_sizes; (void)n_in; (void)out_size;
    const float* x   = (const float*)d_in[0];
    const int*   ei  = (const int*)d_in[1];
    const int*   bat = (const int*)d_in[2];
    const float* W1  = (const float*)d_in[3];
    const float* as1 = (const float*)d_in[4];
    const float* ad1 = (const float*)d_in[5];
    const float* b1  = (const float*)d_in[6];
    const float* W2  = (const float*)d_in[7];
    const float* as2 = (const float*)d_in[8];
    const float* ad2 = (const float*)d_in[9];
    const float* b2  = (const float*)d_in[10];
    const float* W3  = (const float*)d_in[11];
    const float* as3 = (const float*)d_in[12];
    const float* ad3 = (const float*)d_in[13];
    const float* b3  = (const float*)d_in[14];
    const float* fcW = (const float*)d_in[15];
    const float* fcb = (const float*)d_in[16];
    float* out = (float*)d_out;

    // CSR build + zeroing
    k_init   <<<(NN + 255) / 256, 256>>>();
    k_count  <<<(EE + 255) / 256, 256>>>(ei);
    k_bsum   <<<SCAN_NB, SCAN_B>>>();
    k_bscan  <<<1, 128>>>();
    k_csr    <<<SCAN_NB, SCAN_B>>>();
    k_scatter<<<(EE + 255) / 256, 256>>>(ei);

    dim3 ggrid((NN + 127) / 128, HID / 128);
    int wblocks = (NN * 32 + 255) / 256;

    // layer 1: A = x (K=64)
    k_gemm <<<ggrid, 256>>>(x, W1, INC, 0);
    k_score<<<wblocks, 256>>>(as1, ad1);
    k_agg  <<<wblocks, 256>>>(b1, 1);

    // layer 2: A = g_x1 (K=256)
    k_gemm <<<ggrid, 256>>>(x, W2, HID, 1);
    k_score<<<wblocks, 256>>>(as2, ad2);
    k_agg  <<<wblocks, 256>>>(b2, 2);

    // layer 3: A = g_x2 (K=256), residual += g_x1
    k_gemm <<<ggrid, 256>>>(x, W3, HID, 2);
    k_score<<<wblocks, 256>>>(as3, ad3);
    k_agg  <<<wblocks, 256>>>(b3, 3);

    // pool + fc
    k_pool<<<(NN + 127) / 128, 256>>>(bat);
    k_fc  <<<(NG * NCLS + 255) / 256, 256>>>(fcW, fcb, out);
}